// round 1
// baseline (speedup 1.0000x reference)
#include <cuda_runtime.h>
#include <cstdint>

// GCMCGraphConv: h[dst] += weight[src]*cj[src]; out = h * ci
// N=100000 nodes, F=128 feats, E=1600000 edges (shapes taken from in_sizes).

#define FEAT 128

__global__ void zero_kernel(float4* __restrict__ out, int n4) {
    int i = blockIdx.x * blockDim.x + threadIdx.x;
    if (i < n4) out[i] = make_float4(0.f, 0.f, 0.f, 0.f);
}

// One warp per edge. Lane l handles feats [4l, 4l+4).
__global__ void scatter_kernel(const float* __restrict__ weight,
                               const float* __restrict__ cj,
                               const int* __restrict__ src,
                               const int* __restrict__ dst,
                               float* __restrict__ h,
                               int n_edges) {
    int warp = (blockIdx.x * blockDim.x + threadIdx.x) >> 5;
    int lane = threadIdx.x & 31;
    if (warp >= n_edges) return;

    int s = __ldg(&src[warp]);   // warp-uniform -> L1 broadcast
    int d = __ldg(&dst[warp]);
    float c = __ldg(&cj[s]);

    const float4* wrow = reinterpret_cast<const float4*>(weight + (size_t)s * FEAT);
    float4 v = __ldg(&wrow[lane]);
    v.x *= c; v.y *= c; v.z *= c; v.w *= c;

    float* out = h + (size_t)d * FEAT + lane * 4;
    // Vector fp32 reduction (sm_90+): one L2 atomic op per 16B, no return value.
    asm volatile("red.global.add.v4.f32 [%0], {%1, %2, %3, %4};"
                 :: "l"(out), "f"(v.x), "f"(v.y), "f"(v.z), "f"(v.w)
                 : "memory");
}

// One warp per node row: h *= ci[row]
__global__ void scale_kernel(float* __restrict__ h,
                             const float* __restrict__ ci,
                             int n_nodes) {
    int warp = (blockIdx.x * blockDim.x + threadIdx.x) >> 5;
    int lane = threadIdx.x & 31;
    if (warp >= n_nodes) return;
    float c = __ldg(&ci[warp]);
    float4* row = reinterpret_cast<float4*>(h + (size_t)warp * FEAT);
    float4 v = row[lane];
    v.x *= c; v.y *= c; v.z *= c; v.w *= c;
    row[lane] = v;
}

extern "C" void kernel_launch(void* const* d_in, const int* in_sizes, int n_in,
                              void* d_out, int out_size) {
    const float* weight = (const float*)d_in[0];
    const float* cj     = (const float*)d_in[1];
    const float* ci     = (const float*)d_in[2];
    const int*   src    = (const int*)d_in[3];
    const int*   dst    = (const int*)d_in[4];
    float* h = (float*)d_out;

    int n_nodes = in_sizes[1];          // cj has N elements
    int n_edges = in_sizes[3];

    // 1. zero the accumulator (d_out is poisoned)
    int n4 = out_size / 4;
    zero_kernel<<<(n4 + 255) / 256, 256>>>((float4*)h, n4);

    // 2. edge-parallel scatter: one warp per edge
    {
        int threads = 256;
        long long total_threads = (long long)n_edges * 32;
        int blocks = (int)((total_threads + threads - 1) / threads);
        scatter_kernel<<<blocks, threads>>>(weight, cj, src, dst, h, n_edges);
    }

    // 3. dst-side normalize
    {
        int threads = 256;
        long long total_threads = (long long)n_nodes * 32;
        int blocks = (int)((total_threads + threads - 1) / threads);
        scale_kernel<<<blocks, threads>>>(h, ci, n_nodes);
    }
}

// round 5
// speedup vs baseline: 1.8500x; 1.8500x over previous
#include <cuda_runtime.h>
#include <cstdint>

// GCMCGraphConv: h[dst] = ci[dst] * sum_{e: dst[e]=dst} weight[src[e]] * cj[src[e]]
// Strategy: build dst-CSR per launch (hist -> scan -> scatter), then node-parallel
// pull with register accumulation (no fp32 atomics into h at all).

#define FEAT 128
#define N_MAX 131072
#define E_MAX 2097152

__device__ int g_count[N_MAX];
__device__ int g_off[N_MAX];     // exclusive prefix after scan; inclusive after scatter
__device__ int g_csr_src[E_MAX]; // src node id per CSR slot

__global__ void zero_count_kernel(int n) {
    int i = blockIdx.x * blockDim.x + threadIdx.x;
    if (i < n) g_count[i] = 0;
}

__global__ void hist_kernel(const int* __restrict__ dst, int n_edges) {
    int e = blockIdx.x * blockDim.x + threadIdx.x;
    if (e < n_edges) atomicAdd(&g_count[dst[e]], 1);  // no return use -> RED
}

// Single-block exclusive scan over n counts (n up to N_MAX), 1024 threads.
__global__ void scan_kernel(int n) {
    __shared__ int wsum[32];
    __shared__ int carry;
    int tid = threadIdx.x, lane = tid & 31, w = tid >> 5;
    if (tid == 0) carry = 0;
    __syncthreads();
    for (int base = 0; base < n; base += 1024) {
        int i = base + tid;
        int v = (i < n) ? g_count[i] : 0;
        int x = v;
        #pragma unroll
        for (int o = 1; o < 32; o <<= 1) {
            int y = __shfl_up_sync(0xffffffffu, x, o);
            if (lane >= o) x += y;
        }
        if (lane == 31) wsum[w] = x;
        __syncthreads();
        if (w == 0) {
            int s = wsum[lane];
            #pragma unroll
            for (int o = 1; o < 32; o <<= 1) {
                int y = __shfl_up_sync(0xffffffffu, s, o);
                if (lane >= o) s += y;
            }
            wsum[lane] = s;
        }
        __syncthreads();
        int woff = w ? wsum[w - 1] : 0;
        int excl = carry + woff + x - v;
        if (i < n) g_off[i] = excl;
        int total = wsum[31];
        __syncthreads();
        if (tid == 0) carry += total;
        __syncthreads();
    }
}

// Scatter edges into CSR slots. After this, g_off[d] == inclusive prefix (end of segment d).
__global__ void build_csr_kernel(const int* __restrict__ src,
                                 const int* __restrict__ dst,
                                 int n_edges) {
    int e = blockIdx.x * blockDim.x + threadIdx.x;
    if (e < n_edges) {
        int d = dst[e];
        int pos = atomicAdd(&g_off[d], 1);
        g_csr_src[pos] = src[e];
    }
}

// One warp per dst node: accumulate in registers, one write per element.
__global__ void pull_kernel(const float* __restrict__ weight,
                            const float* __restrict__ cj,
                            const float* __restrict__ ci,
                            float* __restrict__ h,
                            int n_nodes) {
    int node = (blockIdx.x * blockDim.x + threadIdx.x) >> 5;
    int lane = threadIdx.x & 31;
    if (node >= n_nodes) return;

    int start = node ? __ldg(&g_off[node - 1]) : 0;
    int end   = __ldg(&g_off[node]);

    float ax = 0.f, ay = 0.f, az = 0.f, aw = 0.f;
    int k = start;
    // Unroll by 4 for memory-level parallelism.
    for (; k + 4 <= end; k += 4) {
        int s0 = __ldg(&g_csr_src[k + 0]);
        int s1 = __ldg(&g_csr_src[k + 1]);
        int s2 = __ldg(&g_csr_src[k + 2]);
        int s3 = __ldg(&g_csr_src[k + 3]);
        float c0 = __ldg(&cj[s0]);
        float c1 = __ldg(&cj[s1]);
        float c2 = __ldg(&cj[s2]);
        float c3 = __ldg(&cj[s3]);
        float4 v0 = __ldg(reinterpret_cast<const float4*>(weight + (size_t)s0 * FEAT) + lane);
        float4 v1 = __ldg(reinterpret_cast<const float4*>(weight + (size_t)s1 * FEAT) + lane);
        float4 v2 = __ldg(reinterpret_cast<const float4*>(weight + (size_t)s2 * FEAT) + lane);
        float4 v3 = __ldg(reinterpret_cast<const float4*>(weight + (size_t)s3 * FEAT) + lane);
        ax += c0 * v0.x + c1 * v1.x + c2 * v2.x + c3 * v3.x;
        ay += c0 * v0.y + c1 * v1.y + c2 * v2.y + c3 * v3.y;
        az += c0 * v0.z + c1 * v1.z + c2 * v2.z + c3 * v3.z;
        aw += c0 * v0.w + c1 * v1.w + c2 * v2.w + c3 * v3.w;
    }
    for (; k < end; k++) {
        int s = __ldg(&g_csr_src[k]);
        float c = __ldg(&cj[s]);
        float4 v = __ldg(reinterpret_cast<const float4*>(weight + (size_t)s * FEAT) + lane);
        ax += c * v.x; ay += c * v.y; az += c * v.z; aw += c * v.w;
    }

    float ciev = __ldg(&ci[node]);
    float4 r;
    r.x = ax * ciev; r.y = ay * ciev; r.z = az * ciev; r.w = aw * ciev;
    reinterpret_cast<float4*>(h + (size_t)node * FEAT)[lane] = r;
}

extern "C" void kernel_launch(void* const* d_in, const int* in_sizes, int n_in,
                              void* d_out, int out_size) {
    const float* weight = (const float*)d_in[0];
    const float* cj     = (const float*)d_in[1];
    const float* ci     = (const float*)d_in[2];
    const int*   src    = (const int*)d_in[3];
    const int*   dst    = (const int*)d_in[4];
    float* h = (float*)d_out;

    int n_nodes = in_sizes[1];   // cj has N elements
    int n_edges = in_sizes[3];

    // 1. zero per-node counters (device-global scratch must be reset every launch)
    zero_count_kernel<<<(n_nodes + 255) / 256, 256>>>(n_nodes);

    // 2. histogram of dst
    hist_kernel<<<(n_edges + 255) / 256, 256>>>(dst, n_edges);

    // 3. exclusive scan -> g_off
    scan_kernel<<<1, 1024>>>(n_nodes);

    // 4. scatter edges into CSR (g_off becomes inclusive prefix)
    build_csr_kernel<<<(n_edges + 255) / 256, 256>>>(src, dst, n_edges);

    // 5. node-parallel pull, one warp per node (512-thread CTAs = 16 warps)
    {
        long long total_threads = (long long)n_nodes * 32;
        int blocks = (int)((total_threads + 511) / 512);
        pull_kernel<<<blocks, 512>>>(weight, cj, ci, h, n_nodes);
    }
}

// round 8
// speedup vs baseline: 2.8752x; 1.5541x over previous
#include <cuda_runtime.h>
#include <cstdint>

// GCMCGraphConv: h[dst] = ci[dst] * sum_{e: dst[e]=dst} weight[src[e]] * cj[src[e]]
// dst-CSR build (hist -> block-scan -> scatter with fused offset) + node-parallel
// pull with register accumulation. CSR entries pack {src, cj[src]} to keep the
// scattered cj gather out of the hot pull kernel.

#define FEAT 128
#define N_MAX 131072
#define E_MAX 2097152
#define NB_MAX 128   // N_MAX / 1024

__device__ int  g_count[N_MAX];
__device__ int  g_off[N_MAX];       // block-local exclusive prefix; local-inclusive after build
__device__ int  g_bsum[NB_MAX];     // per-block totals
__device__ int  g_bsum_excl[NB_MAX];// exclusive scan of block totals
__device__ int2 g_csr[E_MAX];       // {src, __float_as_int(cj[src])}

__global__ void zero_count_kernel(int n) {
    int i = blockIdx.x * blockDim.x + threadIdx.x;
    if (i < n) g_count[i] = 0;
}

__global__ void hist_kernel(const int* __restrict__ dst, int n_edges) {
    int e = blockIdx.x * blockDim.x + threadIdx.x;
    if (e < n_edges) atomicAdd(&g_count[dst[e]], 1);  // no return use -> RED
}

// Block-local exclusive scan of g_count (1024 elems per block) -> g_off, totals -> g_bsum.
__global__ void scan_block_kernel(int n) {
    __shared__ int wsum[32];
    int tid = threadIdx.x, lane = tid & 31, w = tid >> 5;
    int i = blockIdx.x * 1024 + tid;
    int v = (i < n) ? g_count[i] : 0;
    int x = v;
    #pragma unroll
    for (int o = 1; o < 32; o <<= 1) {
        int y = __shfl_up_sync(0xffffffffu, x, o);
        if (lane >= o) x += y;
    }
    if (lane == 31) wsum[w] = x;
    __syncthreads();
    if (w == 0) {
        int s = wsum[lane];
        #pragma unroll
        for (int o = 1; o < 32; o <<= 1) {
            int y = __shfl_up_sync(0xffffffffu, s, o);
            if (lane >= o) s += y;
        }
        wsum[lane] = s;
    }
    __syncthreads();
    int woff = w ? wsum[w - 1] : 0;
    if (i < n) g_off[i] = woff + x - v;          // exclusive within block
    if (tid == 1023) g_bsum[blockIdx.x] = woff + x;  // block total
}

// Single-block exclusive scan of the (<=128) block totals.
__global__ void scan_bsum_kernel(int nb) {
    __shared__ int wsum[4];
    int tid = threadIdx.x, lane = tid & 31, w = tid >> 5;  // 128 threads
    int v = (tid < nb) ? g_bsum[tid] : 0;
    int x = v;
    #pragma unroll
    for (int o = 1; o < 32; o <<= 1) {
        int y = __shfl_up_sync(0xffffffffu, x, o);
        if (lane >= o) x += y;
    }
    if (lane == 31) wsum[w] = x;
    __syncthreads();
    if (w == 0 && lane < 4) {
        int s = wsum[lane];
        #pragma unroll
        for (int o = 1; o < 4; o <<= 1) {
            int y = __shfl_up_sync(0xfu, s, o);
            if (lane >= o) s += y;
        }
        wsum[lane] = s;
    }
    __syncthreads();
    int woff = w ? wsum[w - 1] : 0;
    g_bsum_excl[tid] = woff + x - v;
}

// Scatter edges into CSR slots, packing {src, cj[src]}.
__global__ void build_csr_kernel(const int* __restrict__ src,
                                 const int* __restrict__ dst,
                                 const float* __restrict__ cj,
                                 int n_edges) {
    int e = blockIdx.x * blockDim.x + threadIdx.x;
    if (e < n_edges) {
        int d = dst[e];
        int pos = atomicAdd(&g_off[d], 1) + __ldg(&g_bsum_excl[d >> 10]);
        int s = src[e];
        float c = __ldg(&cj[s]);
        g_csr[pos] = make_int2(s, __float_as_int(c));
    }
}

__device__ __forceinline__ int seg_end(int node) {
    return __ldg(&g_off[node]) + __ldg(&g_bsum_excl[node >> 10]);
}

// One warp per dst node: accumulate in registers, single write per element.
__global__ void pull_kernel(const float* __restrict__ weight,
                            const float* __restrict__ ci,
                            float* __restrict__ h,
                            int n_nodes) {
    int node = (blockIdx.x * blockDim.x + threadIdx.x) >> 5;
    int lane = threadIdx.x & 31;
    if (node >= n_nodes) return;

    int start = node ? seg_end(node - 1) : 0;
    int end   = seg_end(node);

    float ax = 0.f, ay = 0.f, az = 0.f, aw = 0.f;
    int k = start;
    for (; k + 8 <= end; k += 8) {
        int2 p[8];
        #pragma unroll
        for (int j = 0; j < 8; j++) p[j] = __ldg(&g_csr[k + j]);
        #pragma unroll
        for (int j = 0; j < 8; j++) {
            float c = __int_as_float(p[j].y);
            float4 v = __ldg(reinterpret_cast<const float4*>(weight + (size_t)p[j].x * FEAT) + lane);
            ax += c * v.x; ay += c * v.y; az += c * v.z; aw += c * v.w;
        }
    }
    if (k + 4 <= end) {
        int2 p[4];
        #pragma unroll
        for (int j = 0; j < 4; j++) p[j] = __ldg(&g_csr[k + j]);
        #pragma unroll
        for (int j = 0; j < 4; j++) {
            float c = __int_as_float(p[j].y);
            float4 v = __ldg(reinterpret_cast<const float4*>(weight + (size_t)p[j].x * FEAT) + lane);
            ax += c * v.x; ay += c * v.y; az += c * v.z; aw += c * v.w;
        }
        k += 4;
    }
    for (; k < end; k++) {
        int2 p = __ldg(&g_csr[k]);
        float c = __int_as_float(p.y);
        float4 v = __ldg(reinterpret_cast<const float4*>(weight + (size_t)p.x * FEAT) + lane);
        ax += c * v.x; ay += c * v.y; az += c * v.z; aw += c * v.w;
    }

    float ciev = __ldg(&ci[node]);
    float4 r;
    r.x = ax * ciev; r.y = ay * ciev; r.z = az * ciev; r.w = aw * ciev;
    reinterpret_cast<float4*>(h + (size_t)node * FEAT)[lane] = r;
}

extern "C" void kernel_launch(void* const* d_in, const int* in_sizes, int n_in,
                              void* d_out, int out_size) {
    const float* weight = (const float*)d_in[0];
    const float* cj     = (const float*)d_in[1];
    const float* ci     = (const float*)d_in[2];
    const int*   src    = (const int*)d_in[3];
    const int*   dst    = (const int*)d_in[4];
    float* h = (float*)d_out;

    int n_nodes = in_sizes[1];   // cj has N elements
    int n_edges = in_sizes[3];
    int n_blocks_scan = (n_nodes + 1023) / 1024;

    // 1. zero per-node counters (device-global scratch must be reset every launch)
    zero_count_kernel<<<(n_nodes + 255) / 256, 256>>>(n_nodes);

    // 2. histogram of dst
    hist_kernel<<<(n_edges + 255) / 256, 256>>>(dst, n_edges);

    // 3a. block-local exclusive scan + block totals
    scan_block_kernel<<<n_blocks_scan, 1024>>>(n_nodes);

    // 3b. exclusive scan of block totals (<=128)
    scan_bsum_kernel<<<1, 128>>>(n_blocks_scan);

    // 4. scatter edges into CSR, packing {src, cj[src]}
    build_csr_kernel<<<(n_edges + 255) / 256, 256>>>(src, dst, cj, n_edges);

    // 5. node-parallel pull, one warp per node
    {
        long long total_threads = (long long)n_nodes * 32;
        int blocks = (int)((total_threads + 255) / 256);
        pull_kernel<<<blocks, 256>>>(weight, ci, h, n_nodes);
    }
}